// round 16
// baseline (speedup 1.0000x reference)
#include <cuda_runtime.h>
#include <cuda_bf16.h>
#include <math.h>

// Problem constants
#define B_   8
#define C_   256
#define IC_  128
#define H_   128
#define W_   128
#define H2_  64
#define W2_  64
#define NQ_  4096     // 64*64
#define NKV_ 1024     // 32*32

// ------------------------- scratch (device globals; no allocation) -------------------------
__device__ float d_rgb_p[B_ * C_ * NQ_];      // [B][C][4096]
__device__ float d_ev_p [B_ * C_ * NQ_];      // [B][C][4096]
__device__ float d_theta[B_ * NQ_ * IC_];     // [B][4096][128]
__device__ float d_gconv[B_ * NQ_ * IC_];     // pre-pool g
__device__ float d_pconv[B_ * NQ_ * IC_];     // pre-pool phi
__device__ float d_g    [B_ * NKV_ * IC_];    // [B][1024][128]
__device__ float d_phi  [B_ * NKV_ * IC_];    // [B][1024][128]
__device__ float d_S    [B_ * NQ_ * NKV_];    // [B][4096][1024] unnormalized exp(scores)
__device__ float d_y    [B_ * NQ_ * IC_];     // [B][4096][128]
__device__ float d_wy   [B_ * C_ * NQ_];      // [B][256][4096]
__device__ float d_mean [C_];
__device__ float d_rstd [C_];

// ------------------------- helpers -------------------------
// Split a pair of consecutive-k fp32 values into packed bf16x2 hi and lo.
__device__ __forceinline__ void split2(float v0, float v1, unsigned &hi, unsigned &lo) {
    unsigned h;
    asm("cvt.rn.bf16x2.f32 %0, %1, %2;" : "=r"(h) : "f"(v1), "f"(v0));
    float h0 = __uint_as_float(h << 16);
    float h1 = __uint_as_float(h & 0xFFFF0000u);
    float r0 = v0 - h0, r1 = v1 - h1;
    asm("cvt.rn.bf16x2.f32 %0, %1, %2;" : "=r"(lo) : "f"(r1), "f"(r0));
    hi = h;
}

__device__ __forceinline__ void mma16(float* c, const unsigned* a, const unsigned* b) {
    asm volatile(
        "mma.sync.aligned.m16n8k16.row.col.f32.bf16.bf16.f32 "
        "{%0,%1,%2,%3}, {%4,%5,%6,%7}, {%8,%9}, {%0,%1,%2,%3};\n"
        : "+f"(c[0]), "+f"(c[1]), "+f"(c[2]), "+f"(c[3])
        : "r"(a[0]), "r"(a[1]), "r"(a[2]), "r"(a[3]), "r"(b[0]), "r"(b[1]));
}

__device__ __forceinline__ void cpa16(void* s, const void* g) {
    unsigned ss = (unsigned)__cvta_generic_to_shared(s);
    asm volatile("cp.async.cg.shared.global [%0], [%1], 16;\n" :: "r"(ss), "l"(g));
}
#define CP_COMMIT() asm volatile("cp.async.commit_group;\n")
#define CP_WAIT0()  asm volatile("cp.async.wait_group 0;\n" ::: "memory")

#define EXP_SHIFT 20.0f

// ------------------------- generic GEMM infrastructure -------------------------
template<bool KMAJ> struct Tile;
template<> struct Tile<true>  { float d[2][16][132]; };
template<> struct Tile<false> { float d[2][128][20]; };

// ------------------------- 3-term split-bf16 GEMM body -------------------------
// EPI: 0 none, 1 bias per-n, 2 bias per-m, 3 exp(x - EXP_SHIFT) epilogue.
template<bool A_KMAJOR, bool B_KMAJOR, int EPI>
__device__ __forceinline__ void gemm_body(
    const float* __restrict__ Ag, const float* __restrict__ Bg,
    const float* __restrict__ bias, float* __restrict__ Cg,
    int K, int Astride, int Bstride, int Cstride, int m0, int n0,
    Tile<A_KMAJOR>& As, Tile<B_KMAJOR>& Bs)
{
    int tid = threadIdx.x;
    int lane = tid & 31, warp = tid >> 5;
    int wm = warp >> 2, wn = warp & 3;           // 2 x 4 warps; warp tile 64m x 32n
    float acc[4][4][4] = {};
    int nkt = K / 16;

    auto stage = [&](int kt, int bf) {
        if constexpr (A_KMAJOR) {
            #pragma unroll
            for (int i = 0; i < 2; ++i) {
                int o = tid + i * 256;
                int r = o >> 5, c = (o & 31) << 2;
                cpa16(&As.d[bf][r][c], &Ag[(size_t)(kt * 16 + r) * Astride + c]);
            }
        } else {
            #pragma unroll
            for (int i = 0; i < 2; ++i) {
                int o = tid + i * 256;
                int r = o >> 2, c = (o & 3) << 2;
                cpa16(&As.d[bf][r][c], &Ag[(size_t)r * Astride + kt * 16 + c]);
            }
        }
        if constexpr (B_KMAJOR) {
            #pragma unroll
            for (int i = 0; i < 2; ++i) {
                int o = tid + i * 256;
                int r = o >> 5, c = (o & 31) << 2;
                cpa16(&Bs.d[bf][r][c], &Bg[(size_t)(kt * 16 + r) * Bstride + c]);
            }
        } else {
            #pragma unroll
            for (int i = 0; i < 2; ++i) {
                int o = tid + i * 256;
                int r = o >> 2, c = (o & 3) << 2;
                cpa16(&Bs.d[bf][r][c], &Bg[(size_t)r * Bstride + kt * 16 + c]);
            }
        }
    };

    stage(0, 0);
    CP_COMMIT();
    CP_WAIT0();
    __syncthreads();

    for (int kt = 0; kt < nkt; ++kt) {
        int cur = kt & 1;
        if (kt + 1 < nkt) stage(kt + 1, cur ^ 1);
        CP_COMMIT();

        int kb = (lane & 3) * 2;
        unsigned ah[4][4], al[4][4], bh[4][2], bl[4][2];
        #pragma unroll
        for (int mi = 0; mi < 4; ++mi) {
            int mr = wm * 64 + mi * 16 + (lane >> 2);
            if constexpr (A_KMAJOR) {
                split2(As.d[cur][kb][mr],       As.d[cur][kb + 1][mr],       ah[mi][0], al[mi][0]);
                split2(As.d[cur][kb][mr + 8],   As.d[cur][kb + 1][mr + 8],   ah[mi][1], al[mi][1]);
                split2(As.d[cur][kb + 8][mr],   As.d[cur][kb + 9][mr],       ah[mi][2], al[mi][2]);
                split2(As.d[cur][kb + 8][mr + 8], As.d[cur][kb + 9][mr + 8], ah[mi][3], al[mi][3]);
            } else {
                float2 v;
                v = *(const float2*)&As.d[cur][mr][kb];         split2(v.x, v.y, ah[mi][0], al[mi][0]);
                v = *(const float2*)&As.d[cur][mr + 8][kb];     split2(v.x, v.y, ah[mi][1], al[mi][1]);
                v = *(const float2*)&As.d[cur][mr][kb + 8];     split2(v.x, v.y, ah[mi][2], al[mi][2]);
                v = *(const float2*)&As.d[cur][mr + 8][kb + 8]; split2(v.x, v.y, ah[mi][3], al[mi][3]);
            }
        }
        #pragma unroll
        for (int ni = 0; ni < 4; ++ni) {
            int nc = wn * 32 + ni * 8 + (lane >> 2);
            if constexpr (B_KMAJOR) {
                split2(Bs.d[cur][kb][nc],     Bs.d[cur][kb + 1][nc], bh[ni][0], bl[ni][0]);
                split2(Bs.d[cur][kb + 8][nc], Bs.d[cur][kb + 9][nc], bh[ni][1], bl[ni][1]);
            } else {
                float2 v;
                v = *(const float2*)&Bs.d[cur][nc][kb];     split2(v.x, v.y, bh[ni][0], bl[ni][0]);
                v = *(const float2*)&Bs.d[cur][nc][kb + 8]; split2(v.x, v.y, bh[ni][1], bl[ni][1]);
            }
        }
        #pragma unroll
        for (int mi = 0; mi < 4; ++mi)
            #pragma unroll
            for (int ni = 0; ni < 4; ++ni) {
                mma16(acc[mi][ni], al[mi], bh[ni]);   // lo*hi
                mma16(acc[mi][ni], ah[mi], bl[ni]);   // hi*lo
                mma16(acc[mi][ni], ah[mi], bh[ni]);   // hi*hi
            }

        CP_WAIT0();
        __syncthreads();
    }

    #pragma unroll
    for (int mi = 0; mi < 4; ++mi) {
        int r0 = m0 + wm * 64 + mi * 16 + (lane >> 2);
        #pragma unroll
        for (int ni = 0; ni < 4; ++ni) {
            int c0i = n0 + wn * 32 + ni * 8 + 2 * (lane & 3);
            float e0 = acc[mi][ni][0], e1 = acc[mi][ni][1];
            float e2 = acc[mi][ni][2], e3 = acc[mi][ni][3];
            if (EPI == 1) {
                float a0 = bias[c0i], a1 = bias[c0i + 1];
                e0 += a0; e1 += a1; e2 += a0; e3 += a1;
            }
            if (EPI == 2) {
                float a = bias[r0], bb = bias[r0 + 8];
                e0 += a; e1 += a; e2 += bb; e3 += bb;
            }
            if (EPI == 3) {
                e0 = __expf(e0 - EXP_SHIFT); e1 = __expf(e1 - EXP_SHIFT);
                e2 = __expf(e2 - EXP_SHIFT); e3 = __expf(e3 - EXP_SHIFT);
            }
            float2 v0 = { e0, e1 };
            float2 v1 = { e2, e3 };
            *(float2*)&Cg[(size_t)r0 * Cstride + c0i] = v0;
            *(float2*)&Cg[(size_t)(r0 + 8) * Cstride + c0i] = v1;
        }
    }
}

template<bool A_KMAJOR, bool B_KMAJOR, int EPI>
__global__ void __launch_bounds__(256) gemm_tc(
    const float* __restrict__ A, const float* __restrict__ Bm,
    const float* __restrict__ bias, float* __restrict__ Cm,
    int K, int Astride, int Bstride, int Cstride,
    long sAb, long sBb, long sCb)
{
    __shared__ Tile<A_KMAJOR> As;
    __shared__ Tile<B_KMAJOR> Bs;
    int m0 = blockIdx.x * 128, n0 = blockIdx.y * 128;
    int b = blockIdx.z;
    const float* Ag = A + (size_t)b * sAb;
    const float* Bg = Bm + (size_t)b * sBb;
    float* Cg = Cm + (size_t)b * sCb;
    if (A_KMAJOR) Ag += m0; else Ag += (size_t)m0 * Astride;
    if (B_KMAJOR) Bg += n0; else Bg += (size_t)n0 * Bstride;
    gemm_body<A_KMAJOR, B_KMAJOR, EPI>(
        Ag, Bg, bias, Cg, K, Astride, Bstride, Cstride, m0, n0, As, Bs);
}

// merged projection kernel (theta/g/phi), z = proj*8 + b
__global__ void __launch_bounds__(256) gemm_proj(
    const float* __restrict__ rgb_p, const float* __restrict__ ev_p,
    const float* __restrict__ tw, const float* __restrict__ tb,
    const float* __restrict__ gw, const float* __restrict__ gb,
    const float* __restrict__ pw, const float* __restrict__ pb,
    float* __restrict__ theta, float* __restrict__ gconv, float* __restrict__ pconv)
{
    __shared__ Tile<true> As;
    __shared__ Tile<false> Bs;
    int z = blockIdx.z;
    int pz = z >> 3, b = z & 7;
    const float* Aall = (pz == 0) ? rgb_p : ev_p;
    const float* Bw   = (pz == 0) ? tw : (pz == 1 ? gw : pw);
    const float* bias = (pz == 0) ? tb : (pz == 1 ? gb : pb);
    float* Cm         = (pz == 0) ? theta : (pz == 1 ? gconv : pconv);
    int m0 = blockIdx.x * 128;
    const float* Ag = Aall + (size_t)b * C_ * NQ_ + m0;   // k-major [256][4096]
    float* Cg = Cm + (size_t)b * NQ_ * IC_;
    gemm_body<true, false, 1>(Ag, Bw, bias, Cg, C_, NQ_, C_, IC_, m0, 0, As, Bs);
}

// ------------------------- PV GEMM with fused row-normalization -------------------------
__global__ void __launch_bounds__(256) gemm_pv(
    const float* __restrict__ P, const float* __restrict__ G, float* __restrict__ Y)
{
    __shared__ Tile<false> As;           // P tile, m-major [128][20]
    __shared__ Tile<true>  Bs;           // G tile, k-major [16][132]
    __shared__ float rs2[256];
    __shared__ float rsum[128];
    int tid = threadIdx.x;
    int lane = tid & 31, warp = tid >> 5;
    int wm = warp >> 2, wn = warp & 3;
    int m0 = blockIdx.x * 128, b = blockIdx.z;
    const float* Ag = P + (size_t)b * NQ_ * NKV_ + (size_t)m0 * NKV_;
    const float* Bg = G + (size_t)b * NKV_ * IC_;
    float* Cg = Y + ((size_t)b * NQ_ + m0) * IC_;
    float acc[4][4][4] = {};
    float rp = 0.f;
    int srow = tid >> 1, sh = (tid & 1) * 8;

    auto stage = [&](int kt, int bf) {
        #pragma unroll
        for (int i = 0; i < 2; ++i) {
            int o = tid + i * 256;
            int r = o >> 2, c = (o & 3) << 2;
            cpa16(&As.d[bf][r][c], &Ag[(size_t)r * NKV_ + kt * 16 + c]);
        }
        #pragma unroll
        for (int i = 0; i < 2; ++i) {
            int o = tid + i * 256;
            int r = o >> 5, c = (o & 31) << 2;
            cpa16(&Bs.d[bf][r][c], &Bg[(size_t)(kt * 16 + r) * IC_ + c]);
        }
    };

    stage(0, 0);
    CP_COMMIT();
    CP_WAIT0();
    __syncthreads();

    for (int kt = 0; kt < NKV_ / 16; ++kt) {
        int cur = kt & 1;
        if (kt + 1 < NKV_ / 16) stage(kt + 1, cur ^ 1);
        CP_COMMIT();

        #pragma unroll
        for (int j = 0; j < 8; ++j) rp += As.d[cur][srow][sh + j];

        int kb = (lane & 3) * 2;
        unsigned ah[4][4], al[4][4], bh[4][2], bl[4][2];
        #pragma unroll
        for (int mi = 0; mi < 4; ++mi) {
            int mr = wm * 64 + mi * 16 + (lane >> 2);
            float2 v;
            v = *(const float2*)&As.d[cur][mr][kb];         split2(v.x, v.y, ah[mi][0], al[mi][0]);
            v = *(const float2*)&As.d[cur][mr + 8][kb];     split2(v.x, v.y, ah[mi][1], al[mi][1]);
            v = *(const float2*)&As.d[cur][mr][kb + 8];     split2(v.x, v.y, ah[mi][2], al[mi][2]);
            v = *(const float2*)&As.d[cur][mr + 8][kb + 8]; split2(v.x, v.y, ah[mi][3], al[mi][3]);
        }
        #pragma unroll
        for (int ni = 0; ni < 4; ++ni) {
            int nc = wn * 32 + ni * 8 + (lane >> 2);
            split2(Bs.d[cur][kb][nc],     Bs.d[cur][kb + 1][nc], bh[ni][0], bl[ni][0]);
            split2(Bs.d[cur][kb + 8][nc], Bs.d[cur][kb + 9][nc], bh[ni][1], bl[ni][1]);
        }
        #pragma unroll
        for (int mi = 0; mi < 4; ++mi)
            #pragma unroll
            for (int ni = 0; ni < 4; ++ni) {
                mma16(acc[mi][ni], al[mi], bh[ni]);
                mma16(acc[mi][ni], ah[mi], bl[ni]);
                mma16(acc[mi][ni], ah[mi], bh[ni]);
            }

        CP_WAIT0();
        __syncthreads();
    }

    rs2[tid] = rp;
    __syncthreads();
    if (tid < 128) rsum[tid] = rs2[2 * tid] + rs2[2 * tid + 1];
    __syncthreads();

    #pragma unroll
    for (int mi = 0; mi < 4; ++mi) {
        int rr = wm * 64 + mi * 16 + (lane >> 2);
        float inv0 = 1.f / rsum[rr], inv1 = 1.f / rsum[rr + 8];
        #pragma unroll
        for (int ni = 0; ni < 4; ++ni) {
            int c0i = wn * 32 + ni * 8 + 2 * (lane & 3);
            float2 v0 = { acc[mi][ni][0] * inv0, acc[mi][ni][1] * inv0 };
            float2 v1 = { acc[mi][ni][2] * inv1, acc[mi][ni][3] * inv1 };
            *(float2*)&Cg[(size_t)rr * IC_ + c0i] = v0;
            *(float2*)&Cg[(size_t)(rr + 8) * IC_ + c0i] = v1;
        }
    }
}

// ------------------------- 2x2 maxpool NCHW — high-ILP (4 outputs/thread, 4x LDG.128) -------------------------
// blockIdx.y: 0 = rgb, 1 = event.  n = B*C*64*16 per source.
__global__ void pool2_kernel(const float* __restrict__ rgb, const float* __restrict__ ev,
                             float* __restrict__ rgb_o, float* __restrict__ ev_o, int n) {
    int i = blockIdx.x * blockDim.x + threadIdx.x;
    if (i >= n) return;
    const float* in = blockIdx.y ? ev : rgb;
    float* out = blockIdx.y ? ev_o : rgb_o;
    int ow4 = i & 15;                        // group of 4 output cols
    int oh  = (i >> 4) & 63;
    int bc  = i >> 10;
    const float* p = in + ((size_t)bc * H_ + 2 * oh) * W_ + ow4 * 8;
    float4 a0 = *(const float4*)p;
    float4 a1 = *(const float4*)(p + 4);
    float4 c0 = *(const float4*)(p + W_);
    float4 c1 = *(const float4*)(p + W_ + 4);
    float4 r;
    r.x = fmaxf(fmaxf(a0.x, a0.y), fmaxf(c0.x, c0.y));
    r.y = fmaxf(fmaxf(a0.z, a0.w), fmaxf(c0.z, c0.w));
    r.z = fmaxf(fmaxf(a1.x, a1.y), fmaxf(c1.x, c1.y));
    r.w = fmaxf(fmaxf(a1.z, a1.w), fmaxf(c1.z, c1.w));
    *(float4*)&out[((size_t)bc * H2_ + oh) * W2_ + ow4 * 4] = r;
}

// ------------------------- row-pool [B][4096][128] -> [B][1024][128] — 2 float4 units/thread -------------------------
__global__ void poolrows_kernel(const float* __restrict__ in, float* __restrict__ out, int n) {
    int i = blockIdx.x * blockDim.x + threadIdx.x;
    if (i >= n) return;                      // n = B*1024*16 (float4-pair units)
    int ic8 = i & 15;                        // pair of float4 units: cols 8*ic8..8*ic8+7
    int kv  = (i >> 4) & 1023;
    int b   = i >> 14;
    int ph = kv >> 5, pw = kv & 31;
    int s00 = (ph * 2) * 64 + pw * 2;
    const float4* p = (const float4*)(in + ((size_t)b * NQ_ + s00) * IC_) + ic8 * 2;
    float4 a0 = p[0], a1 = p[1];
    float4 c0 = p[32], c1 = p[33];
    float4 d0 = p[64 * 32], d1 = p[64 * 32 + 1];
    float4 e0 = p[65 * 32], e1 = p[65 * 32 + 1];
    float4 r0, r1;
    r0.x = fmaxf(fmaxf(a0.x, c0.x), fmaxf(d0.x, e0.x));
    r0.y = fmaxf(fmaxf(a0.y, c0.y), fmaxf(d0.y, e0.y));
    r0.z = fmaxf(fmaxf(a0.z, c0.z), fmaxf(d0.z, e0.z));
    r0.w = fmaxf(fmaxf(a0.w, c0.w), fmaxf(d0.w, e0.w));
    r1.x = fmaxf(fmaxf(a1.x, c1.x), fmaxf(d1.x, e1.x));
    r1.y = fmaxf(fmaxf(a1.y, c1.y), fmaxf(d1.y, e1.y));
    r1.z = fmaxf(fmaxf(a1.z, c1.z), fmaxf(d1.z, e1.z));
    r1.w = fmaxf(fmaxf(a1.w, c1.w), fmaxf(d1.w, e1.w));
    float4* q = ((float4*)(out + ((size_t)b * NKV_ + kv) * IC_)) + ic8 * 2;
    q[0] = r0;
    q[1] = r1;
}

// ------------------------- BatchNorm stats (deterministic, float4) -------------------------
__global__ void bnstats_kernel() {
    __shared__ float ss[256], ss2[256];
    int co = blockIdx.x, tid = threadIdx.x;
    float s = 0.f, s2 = 0.f;
    for (int i = tid; i < B_ * NQ_ / 4; i += 256) {
        int b = i >> 10, sp = (i & 1023) << 2;
        float4 v = *(const float4*)&d_wy[((size_t)b * C_ + co) * NQ_ + sp];
        s += (v.x + v.y) + (v.z + v.w);
        s2 += (v.x * v.x + v.y * v.y) + (v.z * v.z + v.w * v.w);
    }
    ss[tid] = s; ss2[tid] = s2;
    __syncthreads();
    for (int st = 128; st > 0; st >>= 1) {
        if (tid < st) { ss[tid] += ss[tid + st]; ss2[tid] += ss2[tid + st]; }
        __syncthreads();
    }
    if (tid == 0) {
        const float invN = 1.f / (B_ * NQ_);
        float mean = ss[0] * invN;
        float var  = ss2[0] * invN - mean * mean;
        d_mean[co] = mean;
        d_rstd[co] = rsqrtf(var + 1e-5f);
    }
}

// ------------------------- BN apply + residual + 2x upsample — high-ILP (float4 in, 4x float4 out) -------------------------
__global__ void final_kernel(const float* __restrict__ gamma, const float* __restrict__ beta,
                             float* __restrict__ out, int n) {
    int i = blockIdx.x * blockDim.x + threadIdx.x;
    if (i >= n) return;                      // n = B*C*64*16
    int w4 = i & 15;                         // group of 4 pooled cols: 4*w4..4*w4+3
    int h2 = (i >> 4) & 63;
    int co = (i >> 10) & 255;
    int b  = i >> 18;
    size_t base = ((size_t)b * C_ + co) * NQ_ + h2 * W2_ + 4 * w4;
    float mn = d_mean[co], rs = d_rstd[co], gm = gamma[co], bt = beta[co];
    float4 wyv = *(const float4*)&d_wy[base];
    float4 rgv = *(const float4*)&d_rgb_p[base];
    float v0 = (wyv.x - mn) * rs * gm + bt + rgv.x;
    float v1 = (wyv.y - mn) * rs * gm + bt + rgv.y;
    float v2 = (wyv.z - mn) * rs * gm + bt + rgv.z;
    float v3 = (wyv.w - mn) * rs * gm + bt + rgv.w;
    float4 ra = { v0, v0, v1, v1 };
    float4 rb = { v2, v2, v3, v3 };
    size_t ob = (((size_t)b * C_ + co) * H_ + 2 * h2) * W_ + 8 * w4;
    *(float4*)&out[ob]          = ra;        // row 2*h2, cols 8w4..8w4+3
    *(float4*)&out[ob + 4]      = rb;        // row 2*h2, cols 8w4+4..8w4+7
    *(float4*)&out[ob + W_]     = ra;        // row 2*h2+1
    *(float4*)&out[ob + W_ + 4] = rb;
}

// ------------------------- launch -------------------------
extern "C" void kernel_launch(void* const* d_in, const int* in_sizes, int n_in,
                              void* d_out, int out_size) {
    const float* rgb     = (const float*)d_in[0];
    const float* event_  = (const float*)d_in[1];
    const float* g_w     = (const float*)d_in[2];
    const float* g_b     = (const float*)d_in[3];
    const float* theta_w = (const float*)d_in[4];
    const float* theta_b = (const float*)d_in[5];
    const float* phi_w   = (const float*)d_in[6];
    const float* phi_b   = (const float*)d_in[7];
    const float* W_w     = (const float*)d_in[8];
    const float* W_b     = (const float*)d_in[9];
    const float* bn_g    = (const float*)d_in[10];
    const float* bn_b    = (const float*)d_in[11];
    float* out = (float*)d_out;

    float *rgb_p, *ev_p, *theta, *gconv, *pconv, *g, *phi, *S, *y, *wy;
    cudaGetSymbolAddress((void**)&rgb_p, d_rgb_p);
    cudaGetSymbolAddress((void**)&ev_p,  d_ev_p);
    cudaGetSymbolAddress((void**)&theta, d_theta);
    cudaGetSymbolAddress((void**)&gconv, d_gconv);
    cudaGetSymbolAddress((void**)&pconv, d_pconv);
    cudaGetSymbolAddress((void**)&g,     d_g);
    cudaGetSymbolAddress((void**)&phi,   d_phi);
    cudaGetSymbolAddress((void**)&S,     d_S);
    cudaGetSymbolAddress((void**)&y,     d_y);
    cudaGetSymbolAddress((void**)&wy,    d_wy);

    // 1) initial 2x2 maxpool, both modalities in one launch (y-dim selects source)
    {
        int n = B_ * C_ * H2_ * W2_ / 4;
        dim3 grid((n + 255) / 256, 2);
        pool2_kernel<<<grid, 256>>>(rgb, event_, rgb_p, ev_p, n);
    }
    // 2) merged 1x1 conv projections (theta, g, phi) in one launch
    {
        dim3 grid(NQ_ / 128, 1, 24);
        gemm_proj<<<grid, 256>>>(rgb_p, ev_p, theta_w, theta_b, g_w, g_b,
                                 phi_w, phi_b, theta, gconv, pconv);
    }
    // 3) sub-sample pool for g and phi
    {
        int n = B_ * NKV_ * (IC_ / 8);
        poolrows_kernel<<<(n + 255) / 256, 256>>>(gconv, g,   n);
        poolrows_kernel<<<(n + 255) / 256, 256>>>(pconv, phi, n);
    }
    // 4a) scores + exp fused: S = exp(theta @ phi^T - 20)
    {
        dim3 grid(NQ_ / 128, NKV_ / 128, B_);
        gemm_tc<false, false, 3><<<grid, 256>>>(theta, phi, nullptr, S,
            IC_, IC_, IC_, NKV_, (long)NQ_ * IC_, (long)NKV_ * IC_, (long)NQ_ * NKV_);
    }
    // 4b) PV + row-normalization fused: y = (S @ g) / rowsum(S)
    {
        dim3 grid(NQ_ / 128, 1, B_);
        gemm_pv<<<grid, 256>>>(S, g, y);
    }
    // 5) output conv: wy[b][co][s] = sum_ic W_w[co][ic] y[b][s][ic] + W_b[co]
    {
        dim3 grid(C_ / 128, NQ_ / 128, B_);
        gemm_tc<false, false, 2><<<grid, 256>>>(W_w, y, W_b, wy,
            IC_, IC_, IC_, NQ_, 0, (long)NQ_ * IC_, (long)C_ * NQ_);
    }
    // 6) BN stats
    bnstats_kernel<<<C_, 256>>>();
    // 7) BN apply + residual + 2x upsample
    {
        int n = B_ * C_ * H2_ * W2_ / 4;
        final_kernel<<<(n + 255) / 256, 256>>>(bn_g, bn_b, out, n);
    }
}